// round 4
// baseline (speedup 1.0000x reference)
#include <cuda_runtime.h>
#include <cstdint>

// Problem constants
#define BATCH 32
#define SEQ   4096
#define NDIM  1024
#define MROWS (BATCH * SEQ)          // 131072

// Output layout: [context (B*N)] [attn (B*S)] [coverage_out (B*S)]
#define CTX_OFF 0
#define ATT_OFF (BATCH * NDIM)                       // 32768
#define COV_OFF (BATCH * NDIM + BATCH * SEQ)         // 163840

// Scratch (static device memory; no allocation)
__device__ float g_e[MROWS];          // logits e[b*S+s]
__device__ float g_db[BATCH * NDIM];  // dec_feats + bs + bh

// ---------------------------------------------------------------------------
// helpers
// ---------------------------------------------------------------------------
__device__ __forceinline__ float to_tf32(float x) {
    float r;
    asm("cvt.rna.tf32.f32 %0, %1;" : "=f"(r) : "f"(x));
    return r;
}
__device__ __forceinline__ float tanh_fast(float x) {
    float r;
    asm("tanh.approx.f32 %0, %1;" : "=f"(r) : "f"(x));
    return r;
}
__device__ __forceinline__ void mma_tf32(float* d, const unsigned* a, const unsigned* b) {
    asm volatile(
        "mma.sync.aligned.m16n8k8.row.col.f32.tf32.tf32.f32 "
        "{%0,%1,%2,%3},{%4,%5,%6,%7},{%8,%9},{%0,%1,%2,%3};"
        : "+f"(d[0]), "+f"(d[1]), "+f"(d[2]), "+f"(d[3])
        : "r"(a[0]), "r"(a[1]), "r"(a[2]), "r"(a[3]), "r"(b[0]), "r"(b[1]));
}

// ---------------------------------------------------------------------------
// 0) init: zero logits scratch and the context region of d_out (atomics target)
// ---------------------------------------------------------------------------
__global__ void init_kernel(float* __restrict__ out) {
    int i = blockIdx.x * blockDim.x + threadIdx.x;
    if (i < MROWS) g_e[i] = 0.0f;
    if (i < BATCH * NDIM) out[CTX_OFF + i] = 0.0f;
}

// ---------------------------------------------------------------------------
// 1) dec_feats[b][m] = sum_k dec[b][k] * Ws[m][k] + bs[m] + bh[m]
//    grid (32 b, 32 chunks), 256 threads; warp per 4 outputs, coalesced k reads
// ---------------------------------------------------------------------------
__global__ void dec_feats_kernel(const float* __restrict__ dec,
                                 const float* __restrict__ Ws,
                                 const float* __restrict__ bs,
                                 const float* __restrict__ bh) {
    int b = blockIdx.x;
    int chunk = blockIdx.y;
    int w = threadIdx.x >> 5;
    int lane = threadIdx.x & 31;
    const float* dv = dec + b * NDIM;
#pragma unroll
    for (int j = 0; j < 4; j++) {
        int m = chunk * 32 + w * 4 + j;
        const float* wr = Ws + (size_t)m * NDIM;
        float s = 0.0f;
        for (int k = lane; k < NDIM; k += 32) s += dv[k] * wr[k];
#pragma unroll
        for (int o = 16; o > 0; o >>= 1) s += __shfl_xor_sync(0xffffffffu, s, o);
        if (lane == 0) g_db[b * NDIM + m] = s + bs[m] + bh[m];
    }
}

// ---------------------------------------------------------------------------
// 2) Main fused GEMM: acc[row, col] = enc[row,:] . Wh[col,:]   (TF32 mma.sync)
//    epilogue: e[row] += sum_col v[col] * tanh(acc + db[b][col] + cov[row]*wc[col])
//    Tiles: BM=128, BN=128, BK=16. 256 threads = 8 warps (2x4), warp tile 64x32.
//    grid: (x = N/BN = 8, y = M/BM = 1024)  -> column-blocks co-scheduled per row slice
// ---------------------------------------------------------------------------
#define BM 128
#define BN 128
#define BK 16
#define NKT (NDIM / BK)   // 64

__global__ __launch_bounds__(256)
void attn_gemm_kernel(const float* __restrict__ A,    // enc_states [M,K]
                      const float* __restrict__ Wh,   // [N,K]
                      const float* __restrict__ cov,  // [M]
                      const float* __restrict__ wc,   // [N]
                      const float* __restrict__ v,    // [N]
                      const int*   __restrict__ lens) {
    __shared__ float sA[2][BK][BM + 8];
    __shared__ float sB[2][BK][BN + 8];
    __shared__ float s_e[BM];

    const int bc = blockIdx.x;          // 0..7
    const int br = blockIdx.y;          // 0..1023
    const int b  = br >> 5;             // 32 row-blocks per batch (S/BM = 32)
    const int s0 = (br & 31) * BM;

    // Skip tiles entirely past the valid length: attn there is exactly 0.
    if (s0 >= lens[b]) return;

    const int t = threadIdx.x;
    const int lane = t & 31, wid = t >> 5;
    const int warp_m = wid >> 2, warp_n = wid & 3;   // 2 x 4
    const int g = lane >> 2, tig = lane & 3;

    if (t < BM) s_e[t] = 0.0f;

    const float* Ablk = A  + (size_t)br * BM * NDIM;
    const float* Bblk = Wh + (size_t)bc * BN * NDIM;

    const int lrow = t >> 1;           // 0..127
    const int lk   = (t & 1) * 8;      // 0 or 8

    float acc[4][4][4];
#pragma unroll
    for (int i = 0; i < 4; i++)
#pragma unroll
        for (int j = 0; j < 4; j++)
#pragma unroll
            for (int k = 0; k < 4; k++) acc[i][j][k] = 0.0f;

    // prologue: tile 0 -> buffer 0
    {
        const float* ap = Ablk + (size_t)lrow * NDIM + lk;
        const float* bp = Bblk + (size_t)lrow * NDIM + lk;
        float4 a0 = *(const float4*)ap;
        float4 a1 = *(const float4*)(ap + 4);
        float4 b0 = *(const float4*)bp;
        float4 b1 = *(const float4*)(bp + 4);
        float av[8] = {a0.x, a0.y, a0.z, a0.w, a1.x, a1.y, a1.z, a1.w};
        float bv[8] = {b0.x, b0.y, b0.z, b0.w, b1.x, b1.y, b1.z, b1.w};
#pragma unroll
        for (int j = 0; j < 8; j++) {
            sA[0][lk + j][lrow] = to_tf32(av[j]);
            sB[0][lk + j][lrow] = to_tf32(bv[j]);
        }
    }
    __syncthreads();

    for (int kt = 0; kt < NKT; ++kt) {
        const int buf = kt & 1;
        const bool pf = (kt + 1 < NKT);
        float av[8], bv[8];
        if (pf) {
            const float* ap = Ablk + (size_t)lrow * NDIM + (kt + 1) * BK + lk;
            const float* bp = Bblk + (size_t)lrow * NDIM + (kt + 1) * BK + lk;
            float4 a0 = *(const float4*)ap;
            float4 a1 = *(const float4*)(ap + 4);
            float4 b0 = *(const float4*)bp;
            float4 b1 = *(const float4*)(bp + 4);
            av[0]=a0.x; av[1]=a0.y; av[2]=a0.z; av[3]=a0.w;
            av[4]=a1.x; av[5]=a1.y; av[6]=a1.z; av[7]=a1.w;
            bv[0]=b0.x; bv[1]=b0.y; bv[2]=b0.z; bv[3]=b0.w;
            bv[4]=b1.x; bv[5]=b1.y; bv[6]=b1.z; bv[7]=b1.w;
        }

#pragma unroll
        for (int kk = 0; kk < 2; ++kk) {
            const int k0 = kk * 8;
            unsigned af[4][4], bf[4][2];
#pragma unroll
            for (int mt = 0; mt < 4; mt++) {
                int row = warp_m * 64 + mt * 16 + g;
                af[mt][0] = __float_as_uint(sA[buf][k0 + tig][row]);
                af[mt][1] = __float_as_uint(sA[buf][k0 + tig][row + 8]);
                af[mt][2] = __float_as_uint(sA[buf][k0 + tig + 4][row]);
                af[mt][3] = __float_as_uint(sA[buf][k0 + tig + 4][row + 8]);
            }
#pragma unroll
            for (int nt = 0; nt < 4; nt++) {
                int col = warp_n * 32 + nt * 8 + g;
                bf[nt][0] = __float_as_uint(sB[buf][k0 + tig][col]);
                bf[nt][1] = __float_as_uint(sB[buf][k0 + tig + 4][col]);
            }
#pragma unroll
            for (int mt = 0; mt < 4; mt++)
#pragma unroll
                for (int nt = 0; nt < 4; nt++)
                    mma_tf32(acc[mt][nt], af[mt], bf[nt]);
        }

        if (pf) {
            const int nbuf = buf ^ 1;
#pragma unroll
            for (int j = 0; j < 8; j++) {
                sA[nbuf][lk + j][lrow] = to_tf32(av[j]);
                sB[nbuf][lk + j][lrow] = to_tf32(bv[j]);
            }
            __syncthreads();
        }
    }

    // ---- fused epilogue: tanh + dot with v, reduce over columns ----
    float vv[4][2], ww[4][2], dd[4][2];
#pragma unroll
    for (int nt = 0; nt < 4; nt++)
#pragma unroll
        for (int j = 0; j < 2; j++) {
            int col = bc * BN + warp_n * 32 + nt * 8 + 2 * tig + j;
            vv[nt][j] = v[col];
            ww[nt][j] = wc[col];
            dd[nt][j] = g_db[b * NDIM + col];
        }

#pragma unroll
    for (int mt = 0; mt < 4; mt++) {
#pragma unroll
        for (int h = 0; h < 2; h++) {
            int rl = warp_m * 64 + mt * 16 + g + 8 * h;
            size_t rg = (size_t)br * BM + rl;
            float cv = cov[rg];
            float sum = 0.0f;
#pragma unroll
            for (int nt = 0; nt < 4; nt++)
#pragma unroll
                for (int j = 0; j < 2; j++) {
                    float x = acc[mt][nt][2 * h + j] + dd[nt][j] + cv * ww[nt][j];
                    sum += vv[nt][j] * tanh_fast(x);
                }
            sum += __shfl_xor_sync(0xffffffffu, sum, 1);
            sum += __shfl_xor_sync(0xffffffffu, sum, 2);
            if (tig == 0) atomicAdd(&s_e[rl], sum);
        }
    }
    __syncthreads();
    if (t < BM) atomicAdd(&g_e[(size_t)br * BM + t], s_e[t]);
}

// ---------------------------------------------------------------------------
// 3) masked renormalized softmax per batch row + coverage_out
//    attn = exp(e - max_masked) * mask / sum ; coverage_out = cov + attn
// ---------------------------------------------------------------------------
__global__ void softmax_kernel(const float* __restrict__ cov,
                               const int* __restrict__ lens,
                               float* __restrict__ out) {
    const int b = blockIdx.x;
    const int t = threadIdx.x;  // 256
    __shared__ float red[256];
    const int len = lens[b];

    float ev[16];
    float lmax = -1e30f;
#pragma unroll
    for (int i = 0; i < 16; i++) {
        int s = t + i * 256;
        float e = g_e[b * SEQ + s];
        ev[i] = e;
        if (s < len) lmax = fmaxf(lmax, e);
    }
    red[t] = lmax;
    __syncthreads();
    for (int o = 128; o > 0; o >>= 1) {
        if (t < o) red[t] = fmaxf(red[t], red[t + o]);
        __syncthreads();
    }
    float m = red[0];
    __syncthreads();

    float lsum = 0.0f;
#pragma unroll
    for (int i = 0; i < 16; i++) {
        int s = t + i * 256;
        float x = (s < len) ? __expf(ev[i] - m) : 0.0f;
        ev[i] = x;
        lsum += x;
    }
    red[t] = lsum;
    __syncthreads();
    for (int o = 128; o > 0; o >>= 1) {
        if (t < o) red[t] += red[t + o];
        __syncthreads();
    }
    float inv = 1.0f / red[0];

#pragma unroll
    for (int i = 0; i < 16; i++) {
        int s = t + i * 256;
        float a = ev[i] * inv;
        out[ATT_OFF + b * SEQ + s] = a;
        out[COV_OFF + b * SEQ + s] = cov[b * SEQ + s] + a;
    }
}

// ---------------------------------------------------------------------------
// 4) context[b] = sum_s attn[b,s] * enc[b,s,:]   (skips all-zero attn chunks)
//    grid (32 b, 32 s-chunks of 128), 256 threads, float4 per thread
// ---------------------------------------------------------------------------
__global__ void context_kernel(const float* __restrict__ enc,
                               const float* __restrict__ out_attn,  // d_out+ATT_OFF
                               float* __restrict__ ctx) {           // d_out+CTX_OFF
    const int b = blockIdx.x;
    const int sc = blockIdx.y;
    const int t = threadIdx.x;  // 256
    __shared__ float sa[128];
    if (t < 128) sa[t] = out_attn[b * SEQ + sc * 128 + t];
    int any = __syncthreads_or((t < 128) ? (sa[t] != 0.0f) : 0);
    if (!any) return;

    const float4* base =
        (const float4*)(enc + ((size_t)b * SEQ + sc * 128) * NDIM);
    float4 acc = make_float4(0.f, 0.f, 0.f, 0.f);
#pragma unroll 4
    for (int s = 0; s < 128; s++) {
        float a = sa[s];
        float4 x = base[s * 256 + t];
        acc.x += a * x.x;
        acc.y += a * x.y;
        acc.z += a * x.z;
        acc.w += a * x.w;
    }
    float* c = ctx + b * NDIM + t * 4;
    atomicAdd(c + 0, acc.x);
    atomicAdd(c + 1, acc.y);
    atomicAdd(c + 2, acc.z);
    atomicAdd(c + 3, acc.w);
}

// ---------------------------------------------------------------------------
// launch
// ---------------------------------------------------------------------------
extern "C" void kernel_launch(void* const* d_in, const int* in_sizes, int n_in,
                              void* d_out, int out_size) {
    const float* dec  = (const float*)d_in[0];  // [B,N]
    const float* enc  = (const float*)d_in[1];  // [B,S,N]
    const int*   lens = (const int*)  d_in[2];  // [B]
    const float* cov  = (const float*)d_in[3];  // [B,S]
    const float* Wh   = (const float*)d_in[4];  // [N,N]
    const float* bh   = (const float*)d_in[5];  // [N]
    const float* Ws   = (const float*)d_in[6];  // [N,N]
    const float* bs   = (const float*)d_in[7];  // [N]
    const float* wc   = (const float*)d_in[8];  // [N]
    const float* v    = (const float*)d_in[9];  // [N]
    float* out = (float*)d_out;

    init_kernel<<<(MROWS + 255) / 256, 256>>>(out);
    dec_feats_kernel<<<dim3(BATCH, 32), 256>>>(dec, Ws, bs, bh);
    attn_gemm_kernel<<<dim3(NDIM / BN, MROWS / BM), 256>>>(enc, Wh, cov, wc, v, lens);
    softmax_kernel<<<BATCH, 256>>>(cov, lens, out);
    context_kernel<<<dim3(BATCH, SEQ / 128), 256>>>(enc, out + ATT_OFF, out + CTX_OFF);
}

// round 5
// speedup vs baseline: 1.0011x; 1.0011x over previous
#include <cuda_runtime.h>
#include <cstdint>

// Problem constants
#define BATCH 32
#define SEQ   4096
#define NDIM  1024
#define MROWS (BATCH * SEQ)          // 131072

// Output layout: [context (B*N)] [attn (B*S)] [coverage_out (B*S)]
#define CTX_OFF 0
#define ATT_OFF (BATCH * NDIM)                       // 32768
#define COV_OFF (BATCH * NDIM + BATCH * SEQ)         // 163840

// Scratch (static device memory; no allocation)
__device__ float g_e[MROWS];          // logits e[b*S+s]
__device__ float g_db[BATCH * NDIM];  // dec_feats + bs + bh

// ---------------------------------------------------------------------------
// helpers
// ---------------------------------------------------------------------------
__device__ __forceinline__ float to_tf32(float x) {
    float r;
    asm("cvt.rna.tf32.f32 %0, %1;" : "=f"(r) : "f"(x));
    return r;
}
__device__ __forceinline__ float tanh_fast(float x) {
    float r;
    asm("tanh.approx.f32 %0, %1;" : "=f"(r) : "f"(x));
    return r;
}
__device__ __forceinline__ void mma_tf32(float* d, const unsigned* a, const unsigned* b) {
    asm volatile(
        "mma.sync.aligned.m16n8k8.row.col.f32.tf32.tf32.f32 "
        "{%0,%1,%2,%3},{%4,%5,%6,%7},{%8,%9},{%0,%1,%2,%3};"
        : "+f"(d[0]), "+f"(d[1]), "+f"(d[2]), "+f"(d[3])
        : "r"(a[0]), "r"(a[1]), "r"(a[2]), "r"(a[3]), "r"(b[0]), "r"(b[1]));
}

// ---------------------------------------------------------------------------
// 0) init: zero logits scratch and the context region of d_out (atomics target)
// ---------------------------------------------------------------------------
__global__ void init_kernel(float* __restrict__ out) {
    int i = blockIdx.x * blockDim.x + threadIdx.x;
    if (i < MROWS) g_e[i] = 0.0f;
    if (i < BATCH * NDIM) out[CTX_OFF + i] = 0.0f;
}

// ---------------------------------------------------------------------------
// 1) dec_feats[b][m] = sum_k dec[b][k] * Ws[m][k] + bs[m] + bh[m]
//    grid (32 b, 32 chunks), 256 threads; warp per 4 outputs, coalesced k reads
// ---------------------------------------------------------------------------
__global__ void dec_feats_kernel(const float* __restrict__ dec,
                                 const float* __restrict__ Ws,
                                 const float* __restrict__ bs,
                                 const float* __restrict__ bh) {
    int b = blockIdx.x;
    int chunk = blockIdx.y;
    int w = threadIdx.x >> 5;
    int lane = threadIdx.x & 31;
    const float* dv = dec + b * NDIM;
#pragma unroll
    for (int j = 0; j < 4; j++) {
        int m = chunk * 32 + w * 4 + j;
        const float* wr = Ws + (size_t)m * NDIM;
        float s = 0.0f;
        for (int k = lane; k < NDIM; k += 32) s += dv[k] * wr[k];
#pragma unroll
        for (int o = 16; o > 0; o >>= 1) s += __shfl_xor_sync(0xffffffffu, s, o);
        if (lane == 0) g_db[b * NDIM + m] = s + bs[m] + bh[m];
    }
}

// ---------------------------------------------------------------------------
// 2) Main fused GEMM: acc[row, col] = enc[row,:] . Wh[col,:]   (TF32 mma.sync)
//    epilogue: e[row] += sum_col v[col] * tanh(acc + db[b][col] + cov[row]*wc[col])
//    Tiles: BM=128, BN=128, BK=16. 256 threads = 8 warps (2x4), warp tile 64x32.
//    grid: (x = N/BN = 8, y = M/BM = 1024)  -> column-blocks co-scheduled per row slice
// ---------------------------------------------------------------------------
#define BM 128
#define BN 128
#define BK 16
#define NKT (NDIM / BK)   // 64

__global__ __launch_bounds__(256)
void attn_gemm_kernel(const float* __restrict__ A,    // enc_states [M,K]
                      const float* __restrict__ Wh,   // [N,K]
                      const float* __restrict__ cov,  // [M]
                      const float* __restrict__ wc,   // [N]
                      const float* __restrict__ v,    // [N]
                      const int*   __restrict__ lens) {
    __shared__ float sA[2][BK][BM + 8];
    __shared__ float sB[2][BK][BN + 8];
    __shared__ float s_e[BM];

    const int bc = blockIdx.x;          // 0..7
    const int br = blockIdx.y;          // 0..1023
    const int b  = br >> 5;             // 32 row-blocks per batch (S/BM = 32)
    const int s0 = (br & 31) * BM;

    // Skip tiles entirely past the valid length: attn there is exactly 0.
    if (s0 >= lens[b]) return;

    const int t = threadIdx.x;
    const int lane = t & 31, wid = t >> 5;
    const int warp_m = wid >> 2, warp_n = wid & 3;   // 2 x 4
    const int g = lane >> 2, tig = lane & 3;

    if (t < BM) s_e[t] = 0.0f;

    const float* Ablk = A  + (size_t)br * BM * NDIM;
    const float* Bblk = Wh + (size_t)bc * BN * NDIM;

    const int lrow = t >> 1;           // 0..127
    const int lk   = (t & 1) * 8;      // 0 or 8

    float acc[4][4][4];
#pragma unroll
    for (int i = 0; i < 4; i++)
#pragma unroll
        for (int j = 0; j < 4; j++)
#pragma unroll
            for (int k = 0; k < 4; k++) acc[i][j][k] = 0.0f;

    // prologue: tile 0 -> buffer 0
    {
        const float* ap = Ablk + (size_t)lrow * NDIM + lk;
        const float* bp = Bblk + (size_t)lrow * NDIM + lk;
        float4 a0 = *(const float4*)ap;
        float4 a1 = *(const float4*)(ap + 4);
        float4 b0 = *(const float4*)bp;
        float4 b1 = *(const float4*)(bp + 4);
        float av[8] = {a0.x, a0.y, a0.z, a0.w, a1.x, a1.y, a1.z, a1.w};
        float bv[8] = {b0.x, b0.y, b0.z, b0.w, b1.x, b1.y, b1.z, b1.w};
#pragma unroll
        for (int j = 0; j < 8; j++) {
            sA[0][lk + j][lrow] = to_tf32(av[j]);
            sB[0][lk + j][lrow] = to_tf32(bv[j]);
        }
    }
    __syncthreads();

    for (int kt = 0; kt < NKT; ++kt) {
        const int buf = kt & 1;
        const bool pf = (kt + 1 < NKT);
        float av[8], bv[8];
        if (pf) {
            const float* ap = Ablk + (size_t)lrow * NDIM + (kt + 1) * BK + lk;
            const float* bp = Bblk + (size_t)lrow * NDIM + (kt + 1) * BK + lk;
            float4 a0 = *(const float4*)ap;
            float4 a1 = *(const float4*)(ap + 4);
            float4 b0 = *(const float4*)bp;
            float4 b1 = *(const float4*)(bp + 4);
            av[0]=a0.x; av[1]=a0.y; av[2]=a0.z; av[3]=a0.w;
            av[4]=a1.x; av[5]=a1.y; av[6]=a1.z; av[7]=a1.w;
            bv[0]=b0.x; bv[1]=b0.y; bv[2]=b0.z; bv[3]=b0.w;
            bv[4]=b1.x; bv[5]=b1.y; bv[6]=b1.z; bv[7]=b1.w;
        }

#pragma unroll
        for (int kk = 0; kk < 2; ++kk) {
            const int k0 = kk * 8;
            unsigned af[4][4], bf[4][2];
#pragma unroll
            for (int mt = 0; mt < 4; mt++) {
                int row = warp_m * 64 + mt * 16 + g;
                af[mt][0] = __float_as_uint(sA[buf][k0 + tig][row]);
                af[mt][1] = __float_as_uint(sA[buf][k0 + tig][row + 8]);
                af[mt][2] = __float_as_uint(sA[buf][k0 + tig + 4][row]);
                af[mt][3] = __float_as_uint(sA[buf][k0 + tig + 4][row + 8]);
            }
#pragma unroll
            for (int nt = 0; nt < 4; nt++) {
                int col = warp_n * 32 + nt * 8 + g;
                bf[nt][0] = __float_as_uint(sB[buf][k0 + tig][col]);
                bf[nt][1] = __float_as_uint(sB[buf][k0 + tig + 4][col]);
            }
#pragma unroll
            for (int mt = 0; mt < 4; mt++)
#pragma unroll
                for (int nt = 0; nt < 4; nt++)
                    mma_tf32(acc[mt][nt], af[mt], bf[nt]);
        }

        if (pf) {
            const int nbuf = buf ^ 1;
#pragma unroll
            for (int j = 0; j < 8; j++) {
                sA[nbuf][lk + j][lrow] = to_tf32(av[j]);
                sB[nbuf][lk + j][lrow] = to_tf32(bv[j]);
            }
            __syncthreads();
        }
    }

    // ---- fused epilogue: tanh + dot with v, reduce over columns ----
    float vv[4][2], ww[4][2], dd[4][2];
#pragma unroll
    for (int nt = 0; nt < 4; nt++)
#pragma unroll
        for (int j = 0; j < 2; j++) {
            int col = bc * BN + warp_n * 32 + nt * 8 + 2 * tig + j;
            vv[nt][j] = v[col];
            ww[nt][j] = wc[col];
            dd[nt][j] = g_db[b * NDIM + col];
        }

#pragma unroll
    for (int mt = 0; mt < 4; mt++) {
#pragma unroll
        for (int h = 0; h < 2; h++) {
            int rl = warp_m * 64 + mt * 16 + g + 8 * h;
            size_t rg = (size_t)br * BM + rl;
            float cv = cov[rg];
            float sum = 0.0f;
#pragma unroll
            for (int nt = 0; nt < 4; nt++)
#pragma unroll
                for (int j = 0; j < 2; j++) {
                    float x = acc[mt][nt][2 * h + j] + dd[nt][j] + cv * ww[nt][j];
                    sum += vv[nt][j] * tanh_fast(x);
                }
            sum += __shfl_xor_sync(0xffffffffu, sum, 1);
            sum += __shfl_xor_sync(0xffffffffu, sum, 2);
            if (tig == 0) atomicAdd(&s_e[rl], sum);
        }
    }
    __syncthreads();
    if (t < BM) atomicAdd(&g_e[(size_t)br * BM + t], s_e[t]);
}

// ---------------------------------------------------------------------------
// 3) masked renormalized softmax per batch row + coverage_out
//    attn = exp(e - max_masked) * mask / sum ; coverage_out = cov + attn
// ---------------------------------------------------------------------------
__global__ void softmax_kernel(const float* __restrict__ cov,
                               const int* __restrict__ lens,
                               float* __restrict__ out) {
    const int b = blockIdx.x;
    const int t = threadIdx.x;  // 256
    __shared__ float red[256];
    const int len = lens[b];

    float ev[16];
    float lmax = -1e30f;
#pragma unroll
    for (int i = 0; i < 16; i++) {
        int s = t + i * 256;
        float e = g_e[b * SEQ + s];
        ev[i] = e;
        if (s < len) lmax = fmaxf(lmax, e);
    }
    red[t] = lmax;
    __syncthreads();
    for (int o = 128; o > 0; o >>= 1) {
        if (t < o) red[t] = fmaxf(red[t], red[t + o]);
        __syncthreads();
    }
    float m = red[0];
    __syncthreads();

    float lsum = 0.0f;
#pragma unroll
    for (int i = 0; i < 16; i++) {
        int s = t + i * 256;
        float x = (s < len) ? __expf(ev[i] - m) : 0.0f;
        ev[i] = x;
        lsum += x;
    }
    red[t] = lsum;
    __syncthreads();
    for (int o = 128; o > 0; o >>= 1) {
        if (t < o) red[t] += red[t + o];
        __syncthreads();
    }
    float inv = 1.0f / red[0];

#pragma unroll
    for (int i = 0; i < 16; i++) {
        int s = t + i * 256;
        float a = ev[i] * inv;
        out[ATT_OFF + b * SEQ + s] = a;
        out[COV_OFF + b * SEQ + s] = cov[b * SEQ + s] + a;
    }
}

// ---------------------------------------------------------------------------
// 4) context[b] = sum_s attn[b,s] * enc[b,s,:]   (skips all-zero attn chunks)
//    grid (32 b, 32 s-chunks of 128), 256 threads, float4 per thread
// ---------------------------------------------------------------------------
__global__ void context_kernel(const float* __restrict__ enc,
                               const float* __restrict__ out_attn,  // d_out+ATT_OFF
                               float* __restrict__ ctx) {           // d_out+CTX_OFF
    const int b = blockIdx.x;
    const int sc = blockIdx.y;
    const int t = threadIdx.x;  // 256
    __shared__ float sa[128];
    if (t < 128) sa[t] = out_attn[b * SEQ + sc * 128 + t];
    int any = __syncthreads_or((t < 128) ? (sa[t] != 0.0f) : 0);
    if (!any) return;

    const float4* base =
        (const float4*)(enc + ((size_t)b * SEQ + sc * 128) * NDIM);
    float4 acc = make_float4(0.f, 0.f, 0.f, 0.f);
#pragma unroll 4
    for (int s = 0; s < 128; s++) {
        float a = sa[s];
        float4 x = base[s * 256 + t];
        acc.x += a * x.x;
        acc.y += a * x.y;
        acc.z += a * x.z;
        acc.w += a * x.w;
    }
    float* c = ctx + b * NDIM + t * 4;
    atomicAdd(c + 0, acc.x);
    atomicAdd(c + 1, acc.y);
    atomicAdd(c + 2, acc.z);
    atomicAdd(c + 3, acc.w);
}

// ---------------------------------------------------------------------------
// launch
// ---------------------------------------------------------------------------
extern "C" void kernel_launch(void* const* d_in, const int* in_sizes, int n_in,
                              void* d_out, int out_size) {
    const float* dec  = (const float*)d_in[0];  // [B,N]
    const float* enc  = (const float*)d_in[1];  // [B,S,N]
    const int*   lens = (const int*)  d_in[2];  // [B]
    const float* cov  = (const float*)d_in[3];  // [B,S]
    const float* Wh   = (const float*)d_in[4];  // [N,N]
    const float* bh   = (const float*)d_in[5];  // [N]
    const float* Ws   = (const float*)d_in[6];  // [N,N]
    const float* bs   = (const float*)d_in[7];  // [N]
    const float* wc   = (const float*)d_in[8];  // [N]
    const float* v    = (const float*)d_in[9];  // [N]
    float* out = (float*)d_out;

    init_kernel<<<(MROWS + 255) / 256, 256>>>(out);
    dec_feats_kernel<<<dim3(BATCH, 32), 256>>>(dec, Ws, bs, bh);
    attn_gemm_kernel<<<dim3(NDIM / BN, MROWS / BM), 256>>>(enc, Wh, cov, wc, v, lens);
    softmax_kernel<<<BATCH, 256>>>(cov, lens, out);
    context_kernel<<<dim3(BATCH, SEQ / 128), 256>>>(enc, out + ATT_OFF, out + CTX_OFF);
}

// round 7
// speedup vs baseline: 1.1176x; 1.1164x over previous
#include <cuda_runtime.h>
#include <cstdint>

// Problem constants
#define BATCH 32
#define SEQ   4096
#define NDIM  1024
#define MROWS (BATCH * SEQ)          // 131072

// Output layout: [context (B*N)] [attn (B*S)] [coverage_out (B*S)]
#define CTX_OFF 0
#define ATT_OFF (BATCH * NDIM)                       // 32768
#define COV_OFF (BATCH * NDIM + BATCH * SEQ)         // 163840

// Scratch (static device memory; no allocation)
__device__ float g_e[MROWS];          // logits e[b*S+s]
__device__ float g_db[BATCH * NDIM];  // dec_feats + bs + bh

// ---------------------------------------------------------------------------
// helpers
// ---------------------------------------------------------------------------
__device__ __forceinline__ float tanh_fast(float x) {
    float r;
    asm("tanh.approx.f32 %0, %1;" : "=f"(r) : "f"(x));
    return r;
}
__device__ __forceinline__ uint32_t smem_u32(const void* p) {
    uint32_t a;
    asm("{ .reg .u64 t; cvta.to.shared.u64 t, %1; cvt.u32.u64 %0, t; }"
        : "=r"(a) : "l"(p));
    return a;
}
__device__ __forceinline__ void mma_tf32(float* d, const unsigned* a, const unsigned* b) {
    asm volatile(
        "mma.sync.aligned.m16n8k8.row.col.f32.tf32.tf32.f32 "
        "{%0,%1,%2,%3},{%4,%5,%6,%7},{%8,%9},{%0,%1,%2,%3};"
        : "+f"(d[0]), "+f"(d[1]), "+f"(d[2]), "+f"(d[3])
        : "r"(a[0]), "r"(a[1]), "r"(a[2]), "r"(a[3]), "r"(b[0]), "r"(b[1]));
}
#define CPA16(s, g) \
    asm volatile("cp.async.cg.shared.global [%0], [%1], 16;" :: "r"(s), "l"(g))
#define CPA_COMMIT() asm volatile("cp.async.commit_group;" ::: "memory")

// ---------------------------------------------------------------------------
// 0) init: zero logits scratch and the context region of d_out (atomics target)
// ---------------------------------------------------------------------------
__global__ void init_kernel(float* __restrict__ out) {
    int i = blockIdx.x * blockDim.x + threadIdx.x;
    if (i < MROWS) g_e[i] = 0.0f;
    if (i < BATCH * NDIM) out[CTX_OFF + i] = 0.0f;
}

// ---------------------------------------------------------------------------
// 1) dec_feats[b][m] = sum_k dec[b][k] * Ws[m][k] + bs[m] + bh[m]
// ---------------------------------------------------------------------------
__global__ void dec_feats_kernel(const float* __restrict__ dec,
                                 const float* __restrict__ Ws,
                                 const float* __restrict__ bs,
                                 const float* __restrict__ bh) {
    int b = blockIdx.x;
    int chunk = blockIdx.y;
    int w = threadIdx.x >> 5;
    int lane = threadIdx.x & 31;
    const float* dv = dec + b * NDIM;
#pragma unroll
    for (int j = 0; j < 4; j++) {
        int m = chunk * 32 + w * 4 + j;
        const float* wr = Ws + (size_t)m * NDIM;
        float s = 0.0f;
        for (int k = lane; k < NDIM; k += 32) s += dv[k] * wr[k];
#pragma unroll
        for (int o = 16; o > 0; o >>= 1) s += __shfl_xor_sync(0xffffffffu, s, o);
        if (lane == 0) g_db[b * NDIM + m] = s + bs[m] + bh[m];
    }
}

// ---------------------------------------------------------------------------
// 2) Fused GEMM (tf32 mma.sync, cp.async 3-stage pipeline) + tanh/dot-v epilogue
//    Tiles: BM=128, BN=128, BK=16. 256 threads = 8 warps (2x4), warp tile 64x32.
//    smem: [row][BK+4] per tile (pad 4 -> conflict-free mma gather).
//    grid: (x = N/BN = 8 fastest for A L2-reuse, y = M/BM = 1024)
// ---------------------------------------------------------------------------
#define BM 128
#define BN 128
#define BK 16
#define NKT (NDIM / BK)   // 64
#define NBUF 3
#define LDK (BK + 4)      // 20 floats per row
#define TILE_F (128 * LDK)              // floats per (A or B) stage tile: 2560
#define STAGE_F (2 * TILE_F)            // A+B per stage: 5120 floats
#define SMEM_FLOATS (NBUF * STAGE_F + 128)
#define SMEM_BYTES (SMEM_FLOATS * 4)    // 61952 B

__global__ __launch_bounds__(256, 2)
void attn_gemm_kernel(const float* __restrict__ A,    // enc_states [M,K]
                      const float* __restrict__ Wh,   // [N,K]
                      const float* __restrict__ cov,  // [M]
                      const float* __restrict__ wc,   // [N]
                      const float* __restrict__ v,    // [N]
                      const int*   __restrict__ lens) {
    const int bc = blockIdx.x;          // 0..7
    const int br = blockIdx.y;          // 0..1023
    const int b  = br >> 5;             // S/BM = 32 row-blocks per batch
    if ((br & 31) * BM >= lens[b]) return;   // fully masked tile -> attn == 0

    extern __shared__ float smem[];
    float* s_e = smem + NBUF * STAGE_F;
    const uint32_t sb = smem_u32(smem);

    const int t = threadIdx.x;
    const int lane = t & 31, wid = t >> 5;
    const int warp_m = wid >> 2, warp_n = wid & 3;   // 2 x 4
    const int g = lane >> 2, tig = lane & 3;

    if (t < BM) s_e[t] = 0.0f;

    const float* Ablk = A  + (size_t)br * BM * NDIM;
    const float* Bblk = Wh + (size_t)bc * BN * NDIM;

    // cp.async mapping: 512 x 16B per (A|B) tile; thread does 2 A + 2 B chunks.
    const int lrow = t >> 1;            // 0..127
    const int lch  = (t & 1) * 2;       // chunk pair base: 0 or 2 (chunks of 4 floats)

    float acc[4][4][4];
#pragma unroll
    for (int i = 0; i < 4; i++)
#pragma unroll
        for (int j = 0; j < 4; j++)
#pragma unroll
            for (int k = 0; k < 4; k++) acc[i][j][k] = 0.0f;

    // stage loader: stage p -> buffer p % NBUF
#define LOAD_STAGE(p)                                                          \
    do {                                                                       \
        const int _buf = (p) % NBUF;                                           \
        const uint32_t _ab = sb + (_buf * STAGE_F) * 4;                        \
        const uint32_t _bb = _ab + TILE_F * 4;                                 \
        const int _k0 = (p) * BK;                                              \
        const float* _ag = Ablk + (size_t)lrow * NDIM + _k0 + lch * 4;         \
        const float* _bg = Bblk + (size_t)lrow * NDIM + _k0 + lch * 4;         \
        uint32_t _so = (uint32_t)(lrow * LDK + lch * 4) * 4;                   \
        CPA16(_ab + _so,      _ag);                                            \
        CPA16(_ab + _so + 16, _ag + 4);                                        \
        CPA16(_bb + _so,      _bg);                                            \
        CPA16(_bb + _so + 16, _bg + 4);                                        \
        CPA_COMMIT();                                                          \
    } while (0)

    LOAD_STAGE(0);
    LOAD_STAGE(1);

    for (int s = 0; s < NKT; ++s) {
        if (s + 1 < NKT) {
            asm volatile("cp.async.wait_group 1;" ::: "memory");
        } else {
            asm volatile("cp.async.wait_group 0;" ::: "memory");
        }
        __syncthreads();

        if (s + 2 < NKT) LOAD_STAGE(s + 2);

        const float* sA = smem + (s % NBUF) * STAGE_F;
        const float* sB = sA + TILE_F;

#pragma unroll
        for (int kk = 0; kk < 2; ++kk) {
            const int k0 = kk * 8;
            unsigned af[4][4], bf[4][2];
#pragma unroll
            for (int mt = 0; mt < 4; mt++) {
                int row = warp_m * 64 + mt * 16 + g;
                af[mt][0] = __float_as_uint(sA[row * LDK + k0 + tig]);
                af[mt][1] = __float_as_uint(sA[(row + 8) * LDK + k0 + tig]);
                af[mt][2] = __float_as_uint(sA[row * LDK + k0 + tig + 4]);
                af[mt][3] = __float_as_uint(sA[(row + 8) * LDK + k0 + tig + 4]);
            }
#pragma unroll
            for (int nt = 0; nt < 4; nt++) {
                int col = warp_n * 32 + nt * 8 + g;
                bf[nt][0] = __float_as_uint(sB[col * LDK + k0 + tig]);
                bf[nt][1] = __float_as_uint(sB[col * LDK + k0 + tig + 4]);
            }
#pragma unroll
            for (int mt = 0; mt < 4; mt++)
#pragma unroll
                for (int nt = 0; nt < 4; nt++)
                    mma_tf32(acc[mt][nt], af[mt], bf[nt]);
        }
    }
#undef LOAD_STAGE

    // ---- fused epilogue: tanh + dot with v, reduce over columns ----
    float vv[4][2], ww[4][2], dd[4][2];
#pragma unroll
    for (int nt = 0; nt < 4; nt++)
#pragma unroll
        for (int j = 0; j < 2; j++) {
            int col = bc * BN + warp_n * 32 + nt * 8 + 2 * tig + j;
            vv[nt][j] = v[col];
            ww[nt][j] = wc[col];
            dd[nt][j] = g_db[b * NDIM + col];
        }

#pragma unroll
    for (int mt = 0; mt < 4; mt++) {
#pragma unroll
        for (int h = 0; h < 2; h++) {
            int rl = warp_m * 64 + mt * 16 + g + 8 * h;
            size_t rg = (size_t)br * BM + rl;
            float cv = cov[rg];
            float sum = 0.0f;
#pragma unroll
            for (int nt = 0; nt < 4; nt++)
#pragma unroll
                for (int j = 0; j < 2; j++) {
                    float x = acc[mt][nt][2 * h + j] + dd[nt][j] + cv * ww[nt][j];
                    sum += vv[nt][j] * tanh_fast(x);
                }
            sum += __shfl_xor_sync(0xffffffffu, sum, 1);
            sum += __shfl_xor_sync(0xffffffffu, sum, 2);
            if (tig == 0) atomicAdd(&s_e[rl], sum);
        }
    }
    __syncthreads();
    if (t < BM) atomicAdd(&g_e[(size_t)br * BM + t], s_e[t]);
}

// ---------------------------------------------------------------------------
// 3) masked renormalized softmax per batch row + coverage_out
// ---------------------------------------------------------------------------
__global__ void softmax_kernel(const float* __restrict__ cov,
                               const int* __restrict__ lens,
                               float* __restrict__ out) {
    const int b = blockIdx.x;
    const int t = threadIdx.x;  // 256
    __shared__ float red[256];
    const int len = lens[b];

    float ev[16];
    float lmax = -1e30f;
#pragma unroll
    for (int i = 0; i < 16; i++) {
        int s = t + i * 256;
        float e = g_e[b * SEQ + s];
        ev[i] = e;
        if (s < len) lmax = fmaxf(lmax, e);
    }
    red[t] = lmax;
    __syncthreads();
    for (int o = 128; o > 0; o >>= 1) {
        if (t < o) red[t] = fmaxf(red[t], red[t + o]);
        __syncthreads();
    }
    float m = red[0];
    __syncthreads();

    float lsum = 0.0f;
#pragma unroll
    for (int i = 0; i < 16; i++) {
        int s = t + i * 256;
        float x = (s < len) ? __expf(ev[i] - m) : 0.0f;
        ev[i] = x;
        lsum += x;
    }
    red[t] = lsum;
    __syncthreads();
    for (int o = 128; o > 0; o >>= 1) {
        if (t < o) red[t] += red[t + o];
        __syncthreads();
    }
    float inv = 1.0f / red[0];

#pragma unroll
    for (int i = 0; i < 16; i++) {
        int s = t + i * 256;
        float a = ev[i] * inv;
        out[ATT_OFF + b * SEQ + s] = a;
        out[COV_OFF + b * SEQ + s] = cov[b * SEQ + s] + a;
    }
}

// ---------------------------------------------------------------------------
// 4) context[b] = sum_s attn[b,s] * enc[b,s,:]   (skips all-zero attn chunks)
// ---------------------------------------------------------------------------
__global__ void context_kernel(const float* __restrict__ enc,
                               const float* __restrict__ out_attn,
                               float* __restrict__ ctx) {
    const int b = blockIdx.x;
    const int sc = blockIdx.y;
    const int t = threadIdx.x;  // 256
    __shared__ float sa[128];
    if (t < 128) sa[t] = out_attn[b * SEQ + sc * 128 + t];
    int any = __syncthreads_or((t < 128) ? (sa[t] != 0.0f) : 0);
    if (!any) return;

    const float4* base =
        (const float4*)(enc + ((size_t)b * SEQ + sc * 128) * NDIM);
    float4 acc = make_float4(0.f, 0.f, 0.f, 0.f);
#pragma unroll 4
    for (int s = 0; s < 128; s++) {
        float a = sa[s];
        float4 x = base[s * 256 + t];
        acc.x += a * x.x;
        acc.y += a * x.y;
        acc.z += a * x.z;
        acc.w += a * x.w;
    }
    float* c = ctx + b * NDIM + t * 4;
    atomicAdd(c + 0, acc.x);
    atomicAdd(c + 1, acc.y);
    atomicAdd(c + 2, acc.z);
    atomicAdd(c + 3, acc.w);
}

// ---------------------------------------------------------------------------
// launch
// ---------------------------------------------------------------------------
extern "C" void kernel_launch(void* const* d_in, const int* in_sizes, int n_in,
                              void* d_out, int out_size) {
    const float* dec  = (const float*)d_in[0];  // [B,N]
    const float* enc  = (const float*)d_in[1];  // [B,S,N]
    const int*   lens = (const int*)  d_in[2];  // [B]
    const float* cov  = (const float*)d_in[3];  // [B,S]
    const float* Wh   = (const float*)d_in[4];  // [N,N]
    const float* bh   = (const float*)d_in[5];  // [N]
    const float* Ws   = (const float*)d_in[6];  // [N,N]
    const float* bs   = (const float*)d_in[7];  // [N]
    const float* wc   = (const float*)d_in[8];  // [N]
    const float* v    = (const float*)d_in[9];  // [N]
    float* out = (float*)d_out;

    cudaFuncSetAttribute(attn_gemm_kernel,
                         cudaFuncAttributeMaxDynamicSharedMemorySize, SMEM_BYTES);

    init_kernel<<<(MROWS + 255) / 256, 256>>>(out);
    dec_feats_kernel<<<dim3(BATCH, 32), 256>>>(dec, Ws, bs, bh);
    attn_gemm_kernel<<<dim3(NDIM / BN, MROWS / BM), 256, SMEM_BYTES>>>(enc, Wh, cov, wc,
                                                                       v, lens);
    softmax_kernel<<<BATCH, 256>>>(cov, lens, out);
    context_kernel<<<dim3(BATCH, SEQ / 128), 256>>>(enc, out + ATT_OFF, out + CTX_OFF);
}

// round 8
// speedup vs baseline: 1.1956x; 1.0698x over previous
#include <cuda_runtime.h>
#include <cstdint>

// Problem constants
#define BATCH 32
#define SEQ   4096
#define NDIM  1024
#define MROWS (BATCH * SEQ)          // 131072

// Output layout: [context (B*N)] [attn (B*S)] [coverage_out (B*S)]
#define CTX_OFF 0
#define ATT_OFF (BATCH * NDIM)                       // 32768
#define COV_OFF (BATCH * NDIM + BATCH * SEQ)         // 163840

// Scratch (static device memory; no allocation)
__device__ float g_e[MROWS];          // logits e[b*S+s]
__device__ float g_db[BATCH * NDIM];  // dec_feats + bs + bh

// ---------------------------------------------------------------------------
// helpers
// ---------------------------------------------------------------------------
__device__ __forceinline__ float tanh_fast(float x) {
    float r;
    asm("tanh.approx.f32 %0, %1;" : "=f"(r) : "f"(x));
    return r;
}
__device__ __forceinline__ uint32_t smem_u32(const void* p) {
    uint32_t a;
    asm("{ .reg .u64 t; cvta.to.shared.u64 t, %1; cvt.u32.u64 %0, t; }"
        : "=r"(a) : "l"(p));
    return a;
}
__device__ __forceinline__ void mma_tf32(float* d, const unsigned* a, const unsigned* b) {
    asm volatile(
        "mma.sync.aligned.m16n8k8.row.col.f32.tf32.tf32.f32 "
        "{%0,%1,%2,%3},{%4,%5,%6,%7},{%8,%9},{%0,%1,%2,%3};"
        : "+f"(d[0]), "+f"(d[1]), "+f"(d[2]), "+f"(d[3])
        : "r"(a[0]), "r"(a[1]), "r"(a[2]), "r"(a[3]), "r"(b[0]), "r"(b[1]));
}
#define LDSM_X4(r0, r1, r2, r3, addr) \
    asm volatile("ldmatrix.sync.aligned.m8n8.x4.shared.b16 {%0,%1,%2,%3}, [%4];" \
                 : "=r"(r0), "=r"(r1), "=r"(r2), "=r"(r3) : "r"(addr))
#define CPA16(s, g) \
    asm volatile("cp.async.cg.shared.global [%0], [%1], 16;" :: "r"(s), "l"(g))
#define CPA_COMMIT() asm volatile("cp.async.commit_group;" ::: "memory")

// ---------------------------------------------------------------------------
// 0) init: zero logits scratch and the context region of d_out (atomics target)
// ---------------------------------------------------------------------------
__global__ void init_kernel(float* __restrict__ out) {
    int i = blockIdx.x * blockDim.x + threadIdx.x;
    if (i < MROWS) g_e[i] = 0.0f;
    if (i < BATCH * NDIM) out[CTX_OFF + i] = 0.0f;
}

// ---------------------------------------------------------------------------
// 1) dec_feats[b][m] = sum_k dec[b][k] * Ws[m][k] + bs[m] + bh[m]
// ---------------------------------------------------------------------------
__global__ void dec_feats_kernel(const float* __restrict__ dec,
                                 const float* __restrict__ Ws,
                                 const float* __restrict__ bs,
                                 const float* __restrict__ bh) {
    int b = blockIdx.x;
    int chunk = blockIdx.y;
    int w = threadIdx.x >> 5;
    int lane = threadIdx.x & 31;
    const float* dv = dec + b * NDIM;
#pragma unroll
    for (int j = 0; j < 4; j++) {
        int m = chunk * 32 + w * 4 + j;
        const float* wr = Ws + (size_t)m * NDIM;
        float s = 0.0f;
        for (int k = lane; k < NDIM; k += 32) s += dv[k] * wr[k];
#pragma unroll
        for (int o = 16; o > 0; o >>= 1) s += __shfl_xor_sync(0xffffffffu, s, o);
        if (lane == 0) g_db[b * NDIM + m] = s + bs[m] + bh[m];
    }
}

// ---------------------------------------------------------------------------
// 2) Fused GEMM (tf32 mma.sync + ldmatrix, cp.async 3-stage pipeline)
//    + tanh/dot-v epilogue.
//    Tiles: BM=128, BN=128, BK=16. 256 threads = 8 warps (2x4), warp tile 64x32.
//    smem: [row][BK+4] per tile (pad 4 -> conflict-free LDSM phases).
// ---------------------------------------------------------------------------
#define BM 128
#define BN 128
#define BK 16
#define NKT (NDIM / BK)   // 64
#define NBUF 3
#define LDK (BK + 4)      // 20 floats per row
#define TILE_F (128 * LDK)              // floats per (A or B) stage tile: 2560
#define STAGE_F (2 * TILE_F)            // A+B per stage: 5120 floats
#define SMEM_FLOATS (NBUF * STAGE_F + 128)
#define SMEM_BYTES (SMEM_FLOATS * 4)    // 61952 B

__global__ __launch_bounds__(256, 2)
void attn_gemm_kernel(const float* __restrict__ A,    // enc_states [M,K]
                      const float* __restrict__ Wh,   // [N,K]
                      const float* __restrict__ cov,  // [M]
                      const float* __restrict__ wc,   // [N]
                      const float* __restrict__ v,    // [N]
                      const int*   __restrict__ lens) {
    const int bc = blockIdx.x;          // 0..7
    const int br = blockIdx.y;          // 0..1023
    const int b  = br >> 5;             // S/BM = 32 row-blocks per batch
    if ((br & 31) * BM >= lens[b]) return;   // fully masked tile -> attn == 0

    extern __shared__ float smem[];
    float* s_e = smem + NBUF * STAGE_F;
    const uint32_t sb = smem_u32(smem);

    const int t = threadIdx.x;
    const int lane = t & 31, wid = t >> 5;
    const int warp_m = wid >> 2, warp_n = wid & 3;   // 2 x 4
    const int g = lane >> 2, tig = lane & 3;

    if (t < BM) s_e[t] = 0.0f;

    const float* Ablk = A  + (size_t)br * BM * NDIM;
    const float* Bblk = Wh + (size_t)bc * BN * NDIM;

    // ldmatrix per-thread byte offsets (within a stage tile), kk=0.
    // A x4 (one per mt): lanes 0-15 -> rows 0-15 @ k0, lanes 16-31 -> rows @ k0+4
    uint32_t a_off[4];
#pragma unroll
    for (int mt = 0; mt < 4; mt++) {
        int row = warp_m * 64 + mt * 16 + (lane & 15);
        int kc  = (lane >> 4) * 4;
        a_off[mt] = (uint32_t)(row * LDK + kc) * 4;
    }
    // B x4 (one per nt-pair): quads -> {n0-7@k0, n0-7@k4, n8-15@k0, n8-15@k4}
    uint32_t b_off[2];
#pragma unroll
    for (int p = 0; p < 2; p++) {
        int nrow = warp_n * 32 + p * 16 + (lane & 7) + ((lane >> 4) & 1) * 8;
        int kc   = ((lane >> 3) & 1) * 4;
        b_off[p] = (uint32_t)(TILE_F * 4) + (uint32_t)(nrow * LDK + kc) * 4;
    }

    // cp.async mapping: 512 x 16B per (A|B) tile; thread does 2 A + 2 B chunks.
    const int lrow = t >> 1;            // 0..127
    const int lch  = (t & 1) * 2;       // chunk pair base (chunks of 4 floats)

    float acc[4][4][4];
#pragma unroll
    for (int i = 0; i < 4; i++)
#pragma unroll
        for (int j = 0; j < 4; j++)
#pragma unroll
            for (int k = 0; k < 4; k++) acc[i][j][k] = 0.0f;

#define LOAD_STAGE(p)                                                          \
    do {                                                                       \
        const int _buf = (p) % NBUF;                                           \
        const uint32_t _ab = sb + (_buf * STAGE_F) * 4;                        \
        const uint32_t _bb = _ab + TILE_F * 4;                                 \
        const int _k0 = (p) * BK;                                              \
        const float* _ag = Ablk + (size_t)lrow * NDIM + _k0 + lch * 4;         \
        const float* _bg = Bblk + (size_t)lrow * NDIM + _k0 + lch * 4;         \
        uint32_t _so = (uint32_t)(lrow * LDK + lch * 4) * 4;                   \
        CPA16(_ab + _so,      _ag);                                            \
        CPA16(_ab + _so + 16, _ag + 4);                                        \
        CPA16(_bb + _so,      _bg);                                            \
        CPA16(_bb + _so + 16, _bg + 4);                                        \
        CPA_COMMIT();                                                          \
    } while (0)

    LOAD_STAGE(0);
    LOAD_STAGE(1);

    for (int s = 0; s < NKT; ++s) {
        if (s + 1 < NKT) {
            asm volatile("cp.async.wait_group 1;" ::: "memory");
        } else {
            asm volatile("cp.async.wait_group 0;" ::: "memory");
        }
        __syncthreads();

        if (s + 2 < NKT) LOAD_STAGE(s + 2);

        const uint32_t stage = sb + ((s % NBUF) * STAGE_F) * 4;

#pragma unroll
        for (int kk = 0; kk < 2; ++kk) {
            const uint32_t kofs = stage + kk * 32;   // +8 floats
            unsigned af[4][4], bf[4][2];
#pragma unroll
            for (int mt = 0; mt < 4; mt++)
                LDSM_X4(af[mt][0], af[mt][1], af[mt][2], af[mt][3],
                        kofs + a_off[mt]);
#pragma unroll
            for (int p = 0; p < 2; p++)
                LDSM_X4(bf[2 * p][0], bf[2 * p][1], bf[2 * p + 1][0],
                        bf[2 * p + 1][1], kofs + b_off[p]);
#pragma unroll
            for (int mt = 0; mt < 4; mt++)
#pragma unroll
                for (int nt = 0; nt < 4; nt++)
                    mma_tf32(acc[mt][nt], af[mt], bf[nt]);
        }
    }
#undef LOAD_STAGE

    // ---- fused epilogue: tanh + dot with v, reduce over columns ----
    float vv[4][2], ww[4][2], dd[4][2];
#pragma unroll
    for (int nt = 0; nt < 4; nt++)
#pragma unroll
        for (int j = 0; j < 2; j++) {
            int col = bc * BN + warp_n * 32 + nt * 8 + 2 * tig + j;
            vv[nt][j] = v[col];
            ww[nt][j] = wc[col];
            dd[nt][j] = g_db[b * NDIM + col];
        }

#pragma unroll
    for (int mt = 0; mt < 4; mt++) {
#pragma unroll
        for (int h = 0; h < 2; h++) {
            int rl = warp_m * 64 + mt * 16 + g + 8 * h;
            size_t rg = (size_t)br * BM + rl;
            float cv = cov[rg];
            float sum = 0.0f;
#pragma unroll
            for (int nt = 0; nt < 4; nt++)
#pragma unroll
                for (int j = 0; j < 2; j++) {
                    float x = acc[mt][nt][2 * h + j] + dd[nt][j] + cv * ww[nt][j];
                    sum += vv[nt][j] * tanh_fast(x);
                }
            sum += __shfl_xor_sync(0xffffffffu, sum, 1);
            sum += __shfl_xor_sync(0xffffffffu, sum, 2);
            if (tig == 0) atomicAdd(&s_e[rl], sum);
        }
    }
    __syncthreads();
    if (t < BM) atomicAdd(&g_e[(size_t)br * BM + t], s_e[t]);
}

// ---------------------------------------------------------------------------
// 3) masked renormalized softmax per batch row + coverage_out
// ---------------------------------------------------------------------------
__global__ void softmax_kernel(const float* __restrict__ cov,
                               const int* __restrict__ lens,
                               float* __restrict__ out) {
    const int b = blockIdx.x;
    const int t = threadIdx.x;  // 256
    __shared__ float red[256];
    const int len = lens[b];

    float ev[16];
    float lmax = -1e30f;
#pragma unroll
    for (int i = 0; i < 16; i++) {
        int s = t + i * 256;
        float e = g_e[b * SEQ + s];
        ev[i] = e;
        if (s < len) lmax = fmaxf(lmax, e);
    }
    red[t] = lmax;
    __syncthreads();
    for (int o = 128; o > 0; o >>= 1) {
        if (t < o) red[t] = fmaxf(red[t], red[t + o]);
        __syncthreads();
    }
    float m = red[0];
    __syncthreads();

    float lsum = 0.0f;
#pragma unroll
    for (int i = 0; i < 16; i++) {
        int s = t + i * 256;
        float x = (s < len) ? __expf(ev[i] - m) : 0.0f;
        ev[i] = x;
        lsum += x;
    }
    red[t] = lsum;
    __syncthreads();
    for (int o = 128; o > 0; o >>= 1) {
        if (t < o) red[t] += red[t + o];
        __syncthreads();
    }
    float inv = 1.0f / red[0];

#pragma unroll
    for (int i = 0; i < 16; i++) {
        int s = t + i * 256;
        float a = ev[i] * inv;
        out[ATT_OFF + b * SEQ + s] = a;
        out[COV_OFF + b * SEQ + s] = cov[b * SEQ + s] + a;
    }
}

// ---------------------------------------------------------------------------
// 4) context[b] = sum_s attn[b,s] * enc[b,s,:]   (skips all-zero attn chunks)
// ---------------------------------------------------------------------------
__global__ void context_kernel(const float* __restrict__ enc,
                               const float* __restrict__ out_attn,
                               float* __restrict__ ctx) {
    const int b = blockIdx.x;
    const int sc = blockIdx.y;
    const int t = threadIdx.x;  // 256
    __shared__ float sa[128];
    if (t < 128) sa[t] = out_attn[b * SEQ + sc * 128 + t];
    int any = __syncthreads_or((t < 128) ? (sa[t] != 0.0f) : 0);
    if (!any) return;

    const float4* base =
        (const float4*)(enc + ((size_t)b * SEQ + sc * 128) * NDIM);
    float4 acc = make_float4(0.f, 0.f, 0.f, 0.f);
#pragma unroll 4
    for (int s = 0; s < 128; s++) {
        float a = sa[s];
        float4 x = base[s * 256 + t];
        acc.x += a * x.x;
        acc.y += a * x.y;
        acc.z += a * x.z;
        acc.w += a * x.w;
    }
    float* c = ctx + b * NDIM + t * 4;
    atomicAdd(c + 0, acc.x);
    atomicAdd(c + 1, acc.y);
    atomicAdd(c + 2, acc.z);
    atomicAdd(c + 3, acc.w);
}

// ---------------------------------------------------------------------------
// launch
// ---------------------------------------------------------------------------
extern "C" void kernel_launch(void* const* d_in, const int* in_sizes, int n_in,
                              void* d_out, int out_size) {
    const float* dec  = (const float*)d_in[0];  // [B,N]
    const float* enc  = (const float*)d_in[1];  // [B,S,N]
    const int*   lens = (const int*)  d_in[2];  // [B]
    const float* cov  = (const float*)d_in[3];  // [B,S]
    const float* Wh   = (const float*)d_in[4];  // [N,N]
    const float* bh   = (const float*)d_in[5];  // [N]
    const float* Ws   = (const float*)d_in[6];  // [N,N]
    const float* bs   = (const float*)d_in[7];  // [N]
    const float* wc   = (const float*)d_in[8];  // [N]
    const float* v    = (const float*)d_in[9];  // [N]
    float* out = (float*)d_out;

    cudaFuncSetAttribute(attn_gemm_kernel,
                         cudaFuncAttributeMaxDynamicSharedMemorySize, SMEM_BYTES);

    init_kernel<<<(MROWS + 255) / 256, 256>>>(out);
    dec_feats_kernel<<<dim3(BATCH, 32), 256>>>(dec, Ws, bs, bh);
    attn_gemm_kernel<<<dim3(NDIM / BN, MROWS / BM), 256, SMEM_BYTES>>>(enc, Wh, cov, wc,
                                                                       v, lens);
    softmax_kernel<<<BATCH, 256>>>(cov, lens, out);
    context_kernel<<<dim3(BATCH, SEQ / 128), 256>>>(enc, out + ATT_OFF, out + CTX_OFF);
}

// round 9
// speedup vs baseline: 1.2220x; 1.0221x over previous
#include <cuda_runtime.h>
#include <cstdint>

// Problem constants
#define BATCH 32
#define SEQ   4096
#define NDIM  1024
#define MROWS (BATCH * SEQ)          // 131072

// Output layout: [context (B*N)] [attn (B*S)] [coverage_out (B*S)]
#define CTX_OFF 0
#define ATT_OFF (BATCH * NDIM)                       // 32768
#define COV_OFF (BATCH * NDIM + BATCH * SEQ)         // 163840

// Scratch (static device memory; no allocation)
__device__ float g_e[MROWS];          // logits e[b*S+s]
__device__ float g_db[BATCH * NDIM];  // dec_feats + bs + bh

// ---------------------------------------------------------------------------
// helpers
// ---------------------------------------------------------------------------
__device__ __forceinline__ float tanh_fast(float x) {
    float r;
    asm("tanh.approx.f32 %0, %1;" : "=f"(r) : "f"(x));
    return r;
}
__device__ __forceinline__ uint32_t smem_u32(const void* p) {
    uint32_t a;
    asm("{ .reg .u64 t; cvta.to.shared.u64 t, %1; cvt.u32.u64 %0, t; }"
        : "=r"(a) : "l"(p));
    return a;
}
__device__ __forceinline__ void mma_tf32(float* d, const unsigned* a, const unsigned* b) {
    asm volatile(
        "mma.sync.aligned.m16n8k8.row.col.f32.tf32.tf32.f32 "
        "{%0,%1,%2,%3},{%4,%5,%6,%7},{%8,%9},{%0,%1,%2,%3};"
        : "+f"(d[0]), "+f"(d[1]), "+f"(d[2]), "+f"(d[3])
        : "r"(a[0]), "r"(a[1]), "r"(a[2]), "r"(a[3]), "r"(b[0]), "r"(b[1]));
}
#define LDSM_X4(r0, r1, r2, r3, addr) \
    asm volatile("ldmatrix.sync.aligned.m8n8.x4.shared.b16 {%0,%1,%2,%3}, [%4];" \
                 : "=r"(r0), "=r"(r1), "=r"(r2), "=r"(r3) : "r"(addr))
#define CPA16(s, g) \
    asm volatile("cp.async.cg.shared.global [%0], [%1], 16;" :: "r"(s), "l"(g))
#define CPA_COMMIT() asm volatile("cp.async.commit_group;" ::: "memory")

// ---------------------------------------------------------------------------
// 0) init
// ---------------------------------------------------------------------------
__global__ void init_kernel(float* __restrict__ out) {
    int i = blockIdx.x * blockDim.x + threadIdx.x;
    if (i < MROWS) g_e[i] = 0.0f;
    if (i < BATCH * NDIM) out[CTX_OFF + i] = 0.0f;
}

// ---------------------------------------------------------------------------
// 1) dec_feats[b][m] = sum_k dec[b][k] * Ws[m][k] + bs[m] + bh[m]
// ---------------------------------------------------------------------------
__global__ void dec_feats_kernel(const float* __restrict__ dec,
                                 const float* __restrict__ Ws,
                                 const float* __restrict__ bs,
                                 const float* __restrict__ bh) {
    int b = blockIdx.x;
    int chunk = blockIdx.y;
    int w = threadIdx.x >> 5;
    int lane = threadIdx.x & 31;
    const float* dv = dec + b * NDIM;
#pragma unroll
    for (int j = 0; j < 4; j++) {
        int m = chunk * 32 + w * 4 + j;
        const float* wr = Ws + (size_t)m * NDIM;
        float s = 0.0f;
        for (int k = lane; k < NDIM; k += 32) s += dv[k] * wr[k];
#pragma unroll
        for (int o = 16; o > 0; o >>= 1) s += __shfl_xor_sync(0xffffffffu, s, o);
        if (lane == 0) g_db[b * NDIM + m] = s + bs[m] + bh[m];
    }
}

// ---------------------------------------------------------------------------
// 2) Fused GEMM (tf32 mma.sync + ldmatrix, cp.async 4-stage pipeline)
//    Tiles: BM=128, BN=256, BK=16. 256 threads = 8 warps (2x4), warp tile 64x64.
//    1 CTA/SM, prefetch distance 3 (wait_group 2) -> ~2k cyc latency slack.
// ---------------------------------------------------------------------------
#define BM 128
#define BN 256
#define BK 16
#define NKT (NDIM / BK)   // 64
#define NBUF 4
#define LDK (BK + 4)      // 20 floats per row
#define TILE_A_F (BM * LDK)             // 2560 floats
#define TILE_B_F (BN * LDK)             // 5120 floats
#define STAGE_F (TILE_A_F + TILE_B_F)   // 7680 floats
#define SMEM_FLOATS (NBUF * STAGE_F + 128)
#define SMEM_BYTES (SMEM_FLOATS * 4)    // 123392 B

__global__ __launch_bounds__(256, 1)
void attn_gemm_kernel(const float* __restrict__ A,    // enc_states [M,K]
                      const float* __restrict__ Wh,   // [N,K]
                      const float* __restrict__ cov,  // [M]
                      const float* __restrict__ wc,   // [N]
                      const float* __restrict__ v,    // [N]
                      const int*   __restrict__ lens) {
    const int bc = blockIdx.x;          // 0..3
    const int br = blockIdx.y;          // 0..1023
    const int b  = br >> 5;             // S/BM = 32 row-blocks per batch
    if ((br & 31) * BM >= lens[b]) return;   // fully masked tile -> attn == 0

    extern __shared__ float smem[];
    float* s_e = smem + NBUF * STAGE_F;
    const uint32_t sb = smem_u32(smem);

    const int t = threadIdx.x;
    const int lane = t & 31, wid = t >> 5;
    const int warp_m = wid >> 2, warp_n = wid & 3;   // 2 x 4
    const int g = lane >> 2, tig = lane & 3;

    if (t < BM) s_e[t] = 0.0f;

    const float* Ablk = A  + (size_t)br * BM * NDIM;
    const float* Bblk = Wh + (size_t)bc * BN * NDIM;

    // ldmatrix per-thread byte offsets (within a stage), kk=0.
    uint32_t a_off[4];
#pragma unroll
    for (int mt = 0; mt < 4; mt++) {
        int row = warp_m * 64 + mt * 16 + (lane & 15);
        int kc  = (lane >> 4) * 4;
        a_off[mt] = (uint32_t)(row * LDK + kc) * 4;
    }
    uint32_t b_off[4];
#pragma unroll
    for (int p = 0; p < 4; p++) {
        int nrow = warp_n * 64 + p * 16 + (lane & 7) + ((lane >> 4) & 1) * 8;
        int kc   = ((lane >> 3) & 1) * 4;
        b_off[p] = (uint32_t)(TILE_A_F * 4) + (uint32_t)(nrow * LDK + kc) * 4;
    }

    float acc[4][8][4];
#pragma unroll
    for (int i = 0; i < 4; i++)
#pragma unroll
        for (int j = 0; j < 8; j++)
#pragma unroll
            for (int k = 0; k < 4; k++) acc[i][j][k] = 0.0f;

    // stage loader: A = 512 16B-chunks (2/thread), B = 1024 chunks (4/thread)
#define LOAD_STAGE(p)                                                          \
    do {                                                                       \
        const int _buf = (p) % NBUF;                                           \
        const uint32_t _ab = sb + (_buf * STAGE_F) * 4;                        \
        const uint32_t _bb = _ab + TILE_A_F * 4;                               \
        const int _k0 = (p) * BK;                                              \
        _Pragma("unroll")                                                      \
        for (int _i = 0; _i < 2; _i++) {                                       \
            int _c = t + _i * 256;                                             \
            int _r = _c >> 2, _ch = _c & 3;                                    \
            CPA16(_ab + (uint32_t)(_r * LDK + _ch * 4) * 4,                    \
                  Ablk + (size_t)_r * NDIM + _k0 + _ch * 4);                   \
        }                                                                      \
        _Pragma("unroll")                                                      \
        for (int _i = 0; _i < 4; _i++) {                                       \
            int _c = t + _i * 256;                                             \
            int _r = _c >> 2, _ch = _c & 3;                                    \
            CPA16(_bb + (uint32_t)(_r * LDK + _ch * 4) * 4,                    \
                  Bblk + (size_t)_r * NDIM + _k0 + _ch * 4);                   \
        }                                                                      \
        CPA_COMMIT();                                                          \
    } while (0)

    LOAD_STAGE(0);
    LOAD_STAGE(1);
    LOAD_STAGE(2);

    for (int s = 0; s < NKT; ++s) {
        int rem = NKT - 1 - s;
        if (rem >= 2)      asm volatile("cp.async.wait_group 2;" ::: "memory");
        else if (rem == 1) asm volatile("cp.async.wait_group 1;" ::: "memory");
        else               asm volatile("cp.async.wait_group 0;" ::: "memory");
        __syncthreads();

        if (s + 3 < NKT) LOAD_STAGE(s + 3);

        const uint32_t stage = sb + ((s % NBUF) * STAGE_F) * 4;

#pragma unroll
        for (int kk = 0; kk < 2; ++kk) {
            const uint32_t kofs = stage + kk * 32;   // +8 floats
            unsigned af[4][4], bf[8][2];
#pragma unroll
            for (int mt = 0; mt < 4; mt++)
                LDSM_X4(af[mt][0], af[mt][1], af[mt][2], af[mt][3],
                        kofs + a_off[mt]);
#pragma unroll
            for (int p = 0; p < 4; p++)
                LDSM_X4(bf[2 * p][0], bf[2 * p][1], bf[2 * p + 1][0],
                        bf[2 * p + 1][1], kofs + b_off[p]);
#pragma unroll
            for (int mt = 0; mt < 4; mt++)
#pragma unroll
                for (int nt = 0; nt < 8; nt++)
                    mma_tf32(acc[mt][nt], af[mt], bf[nt]);
        }
    }
#undef LOAD_STAGE

    // ---- fused epilogue: tanh + dot with v, reduce over columns ----
    float vv[8][2], ww[8][2], dd[8][2];
#pragma unroll
    for (int nt = 0; nt < 8; nt++)
#pragma unroll
        for (int j = 0; j < 2; j++) {
            int col = bc * BN + warp_n * 64 + nt * 8 + 2 * tig + j;
            vv[nt][j] = v[col];
            ww[nt][j] = wc[col];
            dd[nt][j] = g_db[b * NDIM + col];
        }

#pragma unroll
    for (int mt = 0; mt < 4; mt++) {
#pragma unroll
        for (int h = 0; h < 2; h++) {
            int rl = warp_m * 64 + mt * 16 + g + 8 * h;
            size_t rg = (size_t)br * BM + rl;
            float cv = cov[rg];
            float sum = 0.0f;
#pragma unroll
            for (int nt = 0; nt < 8; nt++)
#pragma unroll
                for (int j = 0; j < 2; j++) {
                    float x = acc[mt][nt][2 * h + j] + dd[nt][j] + cv * ww[nt][j];
                    sum += vv[nt][j] * tanh_fast(x);
                }
            sum += __shfl_xor_sync(0xffffffffu, sum, 1);
            sum += __shfl_xor_sync(0xffffffffu, sum, 2);
            if (tig == 0) atomicAdd(&s_e[rl], sum);
        }
    }
    __syncthreads();
    if (t < BM) atomicAdd(&g_e[(size_t)br * BM + t], s_e[t]);
}

// ---------------------------------------------------------------------------
// 3) masked renormalized softmax per batch row + coverage_out
// ---------------------------------------------------------------------------
__global__ void softmax_kernel(const float* __restrict__ cov,
                               const int* __restrict__ lens,
                               float* __restrict__ out) {
    const int b = blockIdx.x;
    const int t = threadIdx.x;  // 256
    __shared__ float red[256];
    const int len = lens[b];

    float ev[16];
    float lmax = -1e30f;
#pragma unroll
    for (int i = 0; i < 16; i++) {
        int s = t + i * 256;
        float e = g_e[b * SEQ + s];
        ev[i] = e;
        if (s < len) lmax = fmaxf(lmax, e);
    }
    red[t] = lmax;
    __syncthreads();
    for (int o = 128; o > 0; o >>= 1) {
        if (t < o) red[t] = fmaxf(red[t], red[t + o]);
        __syncthreads();
    }
    float m = red[0];
    __syncthreads();

    float lsum = 0.0f;
#pragma unroll
    for (int i = 0; i < 16; i++) {
        int s = t + i * 256;
        float x = (s < len) ? __expf(ev[i] - m) : 0.0f;
        ev[i] = x;
        lsum += x;
    }
    red[t] = lsum;
    __syncthreads();
    for (int o = 128; o > 0; o >>= 1) {
        if (t < o) red[t] += red[t + o];
        __syncthreads();
    }
    float inv = 1.0f / red[0];

#pragma unroll
    for (int i = 0; i < 16; i++) {
        int s = t + i * 256;
        float a = ev[i] * inv;
        out[ATT_OFF + b * SEQ + s] = a;
        out[COV_OFF + b * SEQ + s] = cov[b * SEQ + s] + a;
    }
}

// ---------------------------------------------------------------------------
// 4) context[b] = sum_s attn[b,s] * enc[b,s,:]   (skips all-zero attn chunks)
// ---------------------------------------------------------------------------
__global__ void context_kernel(const float* __restrict__ enc,
                               const float* __restrict__ out_attn,
                               float* __restrict__ ctx) {
    const int b = blockIdx.x;
    const int sc = blockIdx.y;
    const int t = threadIdx.x;  // 256
    __shared__ float sa[128];
    if (t < 128) sa[t] = out_attn[b * SEQ + sc * 128 + t];
    int any = __syncthreads_or((t < 128) ? (sa[t] != 0.0f) : 0);
    if (!any) return;

    const float4* base =
        (const float4*)(enc + ((size_t)b * SEQ + sc * 128) * NDIM);
    float4 acc = make_float4(0.f, 0.f, 0.f, 0.f);
#pragma unroll 4
    for (int s = 0; s < 128; s++) {
        float a = sa[s];
        float4 x = base[s * 256 + t];
        acc.x += a * x.x;
        acc.y += a * x.y;
        acc.z += a * x.z;
        acc.w += a * x.w;
    }
    float* c = ctx + b * NDIM + t * 4;
    atomicAdd(c + 0, acc.x);
    atomicAdd(c + 1, acc.y);
    atomicAdd(c + 2, acc.z);
    atomicAdd(c + 3, acc.w);
}

// ---------------------------------------------------------------------------
// launch
// ---------------------------------------------------------------------------
extern "C" void kernel_launch(void* const* d_in, const int* in_sizes, int n_in,
                              void* d_out, int out_size) {
    const float* dec  = (const float*)d_in[0];  // [B,N]
    const float* enc  = (const float*)d_in[1];  // [B,S,N]
    const int*   lens = (const int*)  d_in[2];  // [B]
    const float* cov  = (const float*)d_in[3];  // [B,S]
    const float* Wh   = (const float*)d_in[4];  // [N,N]
    const float* bh   = (const float*)d_in[5];  // [N]
    const float* Ws   = (const float*)d_in[6];  // [N,N]
    const float* bs   = (const float*)d_in[7];  // [N]
    const float* wc   = (const float*)d_in[8];  // [N]
    const float* v    = (const float*)d_in[9];  // [N]
    float* out = (float*)d_out;

    cudaFuncSetAttribute(attn_gemm_kernel,
                         cudaFuncAttributeMaxDynamicSharedMemorySize, SMEM_BYTES);

    init_kernel<<<(MROWS + 255) / 256, 256>>>(out);
    dec_feats_kernel<<<dim3(BATCH, 32), 256>>>(dec, Ws, bs, bh);
    attn_gemm_kernel<<<dim3(NDIM / BN, MROWS / BM), 256, SMEM_BYTES>>>(enc, Wh, cov, wc,
                                                                       v, lens);
    softmax_kernel<<<BATCH, 256>>>(cov, lens, out);
    context_kernel<<<dim3(BATCH, SEQ / 128), 256>>>(enc, out + ATT_OFF, out + CTX_OFF);
}

// round 10
// speedup vs baseline: 1.4376x; 1.1764x over previous
#include <cuda_runtime.h>
#include <cstdint>

// Problem constants
#define BATCH 32
#define SEQ   4096
#define NDIM  1024
#define MROWS (BATCH * SEQ)          // 131072

// Output layout: [context (B*N)] [attn (B*S)] [coverage_out (B*S)]
#define CTX_OFF 0
#define ATT_OFF (BATCH * NDIM)                       // 32768
#define COV_OFF (BATCH * NDIM + BATCH * SEQ)         // 163840

// Scratch (static device memory; no allocation).
// g_e4: per-column-block logit partials, written by plain stores (slice per bc).
// Masked rows are never written and stay 0 (BSS) — softmax only reads s < len.
__device__ float g_e4[4 * MROWS];
__device__ float g_db[BATCH * NDIM];  // dec_feats + bs + bh

// ---------------------------------------------------------------------------
// helpers
// ---------------------------------------------------------------------------
__device__ __forceinline__ float tanh_fast(float x) {
    float r;
    asm("tanh.approx.f32 %0, %1;" : "=f"(r) : "f"(x));
    return r;
}
__device__ __forceinline__ uint32_t smem_u32(const void* p) {
    uint32_t a;
    asm("{ .reg .u64 t; cvta.to.shared.u64 t, %1; cvt.u32.u64 %0, t; }"
        : "=r"(a) : "l"(p));
    return a;
}
__device__ __forceinline__ void mma_tf32(float* d, const unsigned* a, const unsigned* b) {
    asm volatile(
        "mma.sync.aligned.m16n8k8.row.col.f32.tf32.tf32.f32 "
        "{%0,%1,%2,%3},{%4,%5,%6,%7},{%8,%9},{%0,%1,%2,%3};"
        : "+f"(d[0]), "+f"(d[1]), "+f"(d[2]), "+f"(d[3])
        : "r"(a[0]), "r"(a[1]), "r"(a[2]), "r"(a[3]), "r"(b[0]), "r"(b[1]));
}
#define LDSM_X4(r0, r1, r2, r3, addr) \
    asm volatile("ldmatrix.sync.aligned.m8n8.x4.shared.b16 {%0,%1,%2,%3}, [%4];" \
                 : "=r"(r0), "=r"(r1), "=r"(r2), "=r"(r3) : "r"(addr))
#define CPA16(s, g) \
    asm volatile("cp.async.cg.shared.global [%0], [%1], 16;" :: "r"(s), "l"(g))
#define CPA_COMMIT() asm volatile("cp.async.commit_group;" ::: "memory")

// ---------------------------------------------------------------------------
// 1) dec_feats[b][m] = sum_k dec[b][k] * Ws[m][k] + bs[m] + bh[m]
// ---------------------------------------------------------------------------
__global__ void dec_feats_kernel(const float* __restrict__ dec,
                                 const float* __restrict__ Ws,
                                 const float* __restrict__ bs,
                                 const float* __restrict__ bh) {
    int b = blockIdx.x;
    int chunk = blockIdx.y;
    int w = threadIdx.x >> 5;
    int lane = threadIdx.x & 31;
    const float* dv = dec + b * NDIM;
#pragma unroll
    for (int j = 0; j < 4; j++) {
        int m = chunk * 32 + w * 4 + j;
        const float* wr = Ws + (size_t)m * NDIM;
        float s = 0.0f;
        for (int k = lane; k < NDIM; k += 32) s += dv[k] * wr[k];
#pragma unroll
        for (int o = 16; o > 0; o >>= 1) s += __shfl_xor_sync(0xffffffffu, s, o);
        if (lane == 0) g_db[b * NDIM + m] = s + bs[m] + bh[m];
    }
}

// ---------------------------------------------------------------------------
// 2) Fused GEMM (tf32 mma.sync + ldmatrix, cp.async 3-buffer pipeline, BK=32)
//    Tiles: BM=128, BN=256, BK=32. 256 threads = 8 warps (2x4), warp tile 64x64.
// ---------------------------------------------------------------------------
#define BM 128
#define BN 256
#define BK 32
#define NKT (NDIM / BK)   // 32
#define NBUF 3
#define LDK (BK + 4)      // 36 floats per row (144B, 16B-aligned; rows hit
                          //  distinct bank phases: 36 mod 32 = 4)
#define TILE_A_F (BM * LDK)             // 4608 floats
#define TILE_B_F (BN * LDK)             // 9216 floats
#define STAGE_F (TILE_A_F + TILE_B_F)   // 13824 floats
#define SMEM_FLOATS (NBUF * STAGE_F + 128)
#define SMEM_BYTES (SMEM_FLOATS * 4)    // 166400 B

__global__ __launch_bounds__(256, 1)
void attn_gemm_kernel(const float* __restrict__ A,    // enc_states [M,K]
                      const float* __restrict__ Wh,   // [N,K]
                      const float* __restrict__ cov,  // [M]
                      const float* __restrict__ wc,   // [N]
                      const float* __restrict__ v,    // [N]
                      const int*   __restrict__ lens) {
    const int bc = blockIdx.x;          // 0..3
    const int br = blockIdx.y;          // 0..1023
    const int b  = br >> 5;             // S/BM = 32 row-blocks per batch
    if ((br & 31) * BM >= lens[b]) return;   // fully masked tile -> attn == 0

    extern __shared__ float smem[];
    float* s_e = smem + NBUF * STAGE_F;
    const uint32_t sb = smem_u32(smem);

    const int t = threadIdx.x;
    const int lane = t & 31, wid = t >> 5;
    const int warp_m = wid >> 2, warp_n = wid & 3;   // 2 x 4
    const int g = lane >> 2, tig = lane & 3;

    if (t < BM) s_e[t] = 0.0f;

    const float* Ablk = A  + (size_t)br * BM * NDIM;
    const float* Bblk = Wh + (size_t)bc * BN * NDIM;

    // ldmatrix per-thread byte offsets (within a stage), kk=0.
    uint32_t a_off[4];
#pragma unroll
    for (int mt = 0; mt < 4; mt++) {
        int row = warp_m * 64 + mt * 16 + (lane & 15);
        int kc  = (lane >> 4) * 4;
        a_off[mt] = (uint32_t)(row * LDK + kc) * 4;
    }
    uint32_t b_off[4];
#pragma unroll
    for (int p = 0; p < 4; p++) {
        int nrow = warp_n * 64 + p * 16 + (lane & 7) + ((lane >> 4) & 1) * 8;
        int kc   = ((lane >> 3) & 1) * 4;
        b_off[p] = (uint32_t)(TILE_A_F * 4) + (uint32_t)(nrow * LDK + kc) * 4;
    }

    float acc[4][8][4];
#pragma unroll
    for (int i = 0; i < 4; i++)
#pragma unroll
        for (int j = 0; j < 8; j++)
#pragma unroll
            for (int k = 0; k < 4; k++) acc[i][j][k] = 0.0f;

    // stage loader: A = 1024 16B-chunks (4/thread), B = 2048 chunks (8/thread)
#define LOAD_STAGE(p)                                                          \
    do {                                                                       \
        const int _buf = (p) % NBUF;                                           \
        const uint32_t _ab = sb + (_buf * STAGE_F) * 4;                        \
        const uint32_t _bb = _ab + TILE_A_F * 4;                               \
        const int _k0 = (p) * BK;                                              \
        _Pragma("unroll")                                                      \
        for (int _i = 0; _i < 4; _i++) {                                       \
            int _c = t + _i * 256;                                             \
            int _r = _c >> 3, _ch = _c & 7;                                    \
            CPA16(_ab + (uint32_t)(_r * LDK + _ch * 4) * 4,                    \
                  Ablk + (size_t)_r * NDIM + _k0 + _ch * 4);                   \
        }                                                                      \
        _Pragma("unroll")                                                      \
        for (int _i = 0; _i < 8; _i++) {                                       \
            int _c = t + _i * 256;                                             \
            int _r = _c >> 3, _ch = _c & 7;                                    \
            CPA16(_bb + (uint32_t)(_r * LDK + _ch * 4) * 4,                    \
                  Bblk + (size_t)_r * NDIM + _k0 + _ch * 4);                   \
        }                                                                      \
        CPA_COMMIT();                                                          \
    } while (0)

    LOAD_STAGE(0);
    LOAD_STAGE(1);

    for (int s = 0; s < NKT; ++s) {
        if (s + 1 < NKT) {
            asm volatile("cp.async.wait_group 1;" ::: "memory");
        } else {
            asm volatile("cp.async.wait_group 0;" ::: "memory");
        }
        __syncthreads();

        if (s + 2 < NKT) LOAD_STAGE(s + 2);

        const uint32_t stage = sb + ((s % NBUF) * STAGE_F) * 4;

#pragma unroll
        for (int kk = 0; kk < 4; ++kk) {
            const uint32_t kofs = stage + kk * 32;   // +8 floats
            unsigned af[4][4], bf[8][2];
#pragma unroll
            for (int mt = 0; mt < 4; mt++)
                LDSM_X4(af[mt][0], af[mt][1], af[mt][2], af[mt][3],
                        kofs + a_off[mt]);
#pragma unroll
            for (int p = 0; p < 4; p++)
                LDSM_X4(bf[2 * p][0], bf[2 * p][1], bf[2 * p + 1][0],
                        bf[2 * p + 1][1], kofs + b_off[p]);
#pragma unroll
            for (int mt = 0; mt < 4; mt++)
#pragma unroll
                for (int nt = 0; nt < 8; nt++)
                    mma_tf32(acc[mt][nt], af[mt], bf[nt]);
        }
    }
#undef LOAD_STAGE

    // ---- fused epilogue: tanh + dot with v, reduce over columns ----
    float vv[8][2], ww[8][2], dd[8][2];
#pragma unroll
    for (int nt = 0; nt < 8; nt++)
#pragma unroll
        for (int j = 0; j < 2; j++) {
            int col = bc * BN + warp_n * 64 + nt * 8 + 2 * tig + j;
            vv[nt][j] = v[col];
            ww[nt][j] = wc[col];
            dd[nt][j] = g_db[b * NDIM + col];
        }

#pragma unroll
    for (int mt = 0; mt < 4; mt++) {
#pragma unroll
        for (int h = 0; h < 2; h++) {
            int rl = warp_m * 64 + mt * 16 + g + 8 * h;
            size_t rg = (size_t)br * BM + rl;
            float cv = cov[rg];
            float sum = 0.0f;
#pragma unroll
            for (int nt = 0; nt < 8; nt++)
#pragma unroll
                for (int j = 0; j < 2; j++) {
                    float x = acc[mt][nt][2 * h + j] + dd[nt][j] + cv * ww[nt][j];
                    sum += vv[nt][j] * tanh_fast(x);
                }
            sum += __shfl_xor_sync(0xffffffffu, sum, 1);
            sum += __shfl_xor_sync(0xffffffffu, sum, 2);
            if (tig == 0) atomicAdd(&s_e[rl], sum);
        }
    }
    __syncthreads();
    // private slice per bc -> plain store (no global atomics, no pre-zero)
    if (t < BM) g_e4[(size_t)bc * MROWS + (size_t)br * BM + t] = s_e[t];
}

// ---------------------------------------------------------------------------
// 3) masked renormalized softmax per batch row + coverage_out (+ ctx zeroing)
// ---------------------------------------------------------------------------
__global__ void softmax_kernel(const float* __restrict__ cov,
                               const int* __restrict__ lens,
                               float* __restrict__ out) {
    const int b = blockIdx.x;
    const int t = threadIdx.x;  // 256
    __shared__ float red[256];
    const int len = lens[b];

    // zero the context region (accumulated by atomics in context_kernel)
#pragma unroll
    for (int i = 0; i < NDIM / 256; i++)
        out[CTX_OFF + b * NDIM + i * 256 + t] = 0.0f;

    float ev[16];
    float lmax = -1e30f;
#pragma unroll
    for (int i = 0; i < 16; i++) {
        int s = t + i * 256;
        size_t idx = (size_t)b * SEQ + s;
        float e = g_e4[idx] + g_e4[MROWS + idx] + g_e4[2 * MROWS + idx] +
                  g_e4[3 * (size_t)MROWS + idx];
        ev[i] = e;
        if (s < len) lmax = fmaxf(lmax, e);
    }
    red[t] = lmax;
    __syncthreads();
    for (int o = 128; o > 0; o >>= 1) {
        if (t < o) red[t] = fmaxf(red[t], red[t + o]);
        __syncthreads();
    }
    float m = red[0];
    __syncthreads();

    float lsum = 0.0f;
#pragma unroll
    for (int i = 0; i < 16; i++) {
        int s = t + i * 256;
        float x = (s < len) ? __expf(ev[i] - m) : 0.0f;
        ev[i] = x;
        lsum += x;
    }
    red[t] = lsum;
    __syncthreads();
    for (int o = 128; o > 0; o >>= 1) {
        if (t < o) red[t] += red[t + o];
        __syncthreads();
    }
    float inv = 1.0f / red[0];

#pragma unroll
    for (int i = 0; i < 16; i++) {
        int s = t + i * 256;
        float a = ev[i] * inv;
        out[ATT_OFF + b * SEQ + s] = a;
        out[COV_OFF + b * SEQ + s] = cov[b * SEQ + s] + a;
    }
}

// ---------------------------------------------------------------------------
// 4) context[b] = sum_s attn[b,s] * enc[b,s,:]   (skips all-zero attn chunks)
// ---------------------------------------------------------------------------
__global__ void context_kernel(const float* __restrict__ enc,
                               const float* __restrict__ out_attn,
                               float* __restrict__ ctx) {
    const int b = blockIdx.x;
    const int sc = blockIdx.y;
    const int t = threadIdx.x;  // 256
    __shared__ float sa[128];
    if (t < 128) sa[t] = out_attn[b * SEQ + sc * 128 + t];
    int any = __syncthreads_or((t < 128) ? (sa[t] != 0.0f) : 0);
    if (!any) return;

    const float4* base =
        (const float4*)(enc + ((size_t)b * SEQ + sc * 128) * NDIM);
    float4 acc = make_float4(0.f, 0.f, 0.f, 0.f);
#pragma unroll 4
    for (int s = 0; s < 128; s++) {
        float a = sa[s];
        float4 x = base[s * 256 + t];
        acc.x += a * x.x;
        acc.y += a * x.y;
        acc.z += a * x.z;
        acc.w += a * x.w;
    }
    float* c = ctx + b * NDIM + t * 4;
    atomicAdd(c + 0, acc.x);
    atomicAdd(c + 1, acc.y);
    atomicAdd(c + 2, acc.z);
    atomicAdd(c + 3, acc.w);
}

// ---------------------------------------------------------------------------
// launch
// ---------------------------------------------------------------------------
extern "C" void kernel_launch(void* const* d_in, const int* in_sizes, int n_in,
                              void* d_out, int out_size) {
    const float* dec  = (const float*)d_in[0];  // [B,N]
    const float* enc  = (const float*)d_in[1];  // [B,S,N]
    const int*   lens = (const int*)  d_in[2];  // [B]
    const float* cov  = (const float*)d_in[3];  // [B,S]
    const float* Wh   = (const float*)d_in[4];  // [N,N]
    const float* bh   = (const float*)d_in[5];  // [N]
    const float* Ws   = (const float*)d_in[6];  // [N,N]
    const float* bs   = (const float*)d_in[7];  // [N]
    const float* wc   = (const float*)d_in[8];  // [N]
    const float* v    = (const float*)d_in[9];  // [N]
    float* out = (float*)d_out;

    cudaFuncSetAttribute(attn_gemm_kernel,
                         cudaFuncAttributeMaxDynamicSharedMemorySize, SMEM_BYTES);

    dec_feats_kernel<<<dim3(BATCH, 32), 256>>>(dec, Ws, bs, bh);
    attn_gemm_kernel<<<dim3(NDIM / BN, MROWS / BM), 256, SMEM_BYTES>>>(enc, Wh, cov, wc,
                                                                       v, lens);
    softmax_kernel<<<BATCH, 256>>>(cov, lens, out);
    context_kernel<<<dim3(BATCH, SEQ / 128), 256>>>(enc, out + ATT_OFF, out + CTX_OFF);
}